// round 14
// baseline (speedup 1.0000x reference)
#include <cuda_runtime.h>
#include <cstddef>

#define BB       32
#define LL       32768
#define CC       128
#define KK       64
#define PADL     31          // SAME, K even: out[t] = sum_k x[t+k-31] * w[k]

#define CH       64          // channels per CTA (half of CC)
#define CQ       16          // channel quads per CTA (float4 groups)
#define TL       64          // output rows per CTA
#define ROWS     128         // x rows staged: [t0-31, t0+96]
#define NTHREADS 128
#define TSUB     8
#define TT       (TL / TSUB) // 8 outputs per thread

#define SMEM_X_F (ROWS * CH)              // 8192 floats = 32 KB
#define SMEM_W_F (KK * CH)                // 4096 floats = 16 KB
#define SMEM_BYTES ((SMEM_X_F + SMEM_W_F) * 4)   // 49152 B -> 4 CTAs/SM

typedef unsigned long long ull;

// Blackwell packed dual-FMA (FFMA2 in SASS): 2x fp32 FMA per issue.
__device__ __forceinline__ ull ffma2(ull a, ull b, ull c) {
    ull d;
    asm("fma.rn.f32x2 %0, %1, %2, %3;" : "=l"(d) : "l"(a), "l"(b), "l"(c));
    return d;
}
__device__ __forceinline__ ull pack2(float lo, float hi) {
    ull r;
    asm("mov.b64 %0, {%1, %2};" : "=l"(r) : "f"(lo), "f"(hi));
    return r;
}

// tanh(x) = 1 - 2/(e^{2x}+1), 5 instructions, branch-free. abs err ~2e-7.
__device__ __forceinline__ float tanh5(float x) {
    float s = x * 2.885390082f;        // 2*log2(e)
    float t, r;
    asm("ex2.approx.f32 %0, %1;" : "=f"(t) : "f"(s));
    float d = t + 1.0f;
    asm("rcp.approx.f32 %0, %1;" : "=f"(r) : "f"(d));
    return __fmaf_rn(-2.0f, r, 1.0f);
}

__global__ __launch_bounds__(NTHREADS, 4)
void dwconv1d_tanh_c4_kernel(const float* __restrict__ x,
                             const float* __restrict__ w,     // [K][CC]
                             const float* __restrict__ bias,  // [CC]
                             float* __restrict__ out) {
    extern __shared__ float sm[];
    float* sx = sm;                  // [ROWS][CH]
    float* sw = sm + SMEM_X_F;       // [KK][CH]

    const int tid  = threadIdx.x;
    const int blk  = blockIdx.x;
    const int half = blk & 1;                 // channel half
    const int tile = (blk >> 1) & 511;        // LL/TL = 512 tiles
    const int b    = blk >> 10;
    const int t0   = tile * TL;

    // ---- stage weights half: 64 rows x 16 float4 ----
    {
        const float4* wsrc = (const float4*)w;    // row stride CC/4 = 32
        float4*       wdst = (float4*)sw;
        #pragma unroll
        for (int n = 0; n < (SMEM_W_F / 4) / NTHREADS; n++) {   // 8 iters
            int idx = tid + n * NTHREADS;         // 0..1023
            int k   = idx >> 4;
            int col = idx & 15;
            wdst[idx] = wsrc[k * 32 + half * 16 + col];
        }
    }

    // ---- stage x half-rows [t0-31, t0+97), zero-padded ----
    {
        const int base = t0 - PADL;
        const float4* xsrc = (const float4*)(x + (size_t)b * LL * CC); // row stride 32 f4
        float4*       xdst = (float4*)sx;                              // row stride 16 f4
        #pragma unroll
        for (int n = 0; n < (SMEM_X_F / 4) / NTHREADS; n++) {   // 16 iters
            int idx = tid + n * NTHREADS;         // 0..2047
            int r   = idx >> 4;
            int col = idx & 15;
            int g   = base + r;
            float4 v = make_float4(0.f, 0.f, 0.f, 0.f);
            if ((unsigned)g < (unsigned)LL)
                v = xsrc[(size_t)g * 32 + half * 16 + col];
            xdst[idx] = v;
        }
    }
    __syncthreads();

    const int c4    = tid & (CQ - 1);   // channel quad within half
    const int ts    = tid >> 4;         // 0..7 time subgroup
    const int jbase = ts * TT;

    // LDS.128 bases; row stride = CQ ulonglong2 (256 B). Immediate offsets.
    const ulonglong2* sx4 = ((const ulonglong2*)sx) + (size_t)jbase * CQ + c4;
    const ulonglong2* sw4 = ((const ulonglong2*)sw) + c4;

    // bias folded into accumulator init
    const float4 bq = ((const float4*)bias)[half * CQ + c4];
    const ull b0 = pack2(bq.x, bq.y);
    const ull b1 = pack2(bq.z, bq.w);
    ull accA[TT], accB[TT];
    #pragma unroll
    for (int j = 0; j < TT; j++) { accA[j] = b0; accB[j] = b1; }

    // Rolling 8-row register window of ulonglong2 (two channel pairs).
    ulonglong2 xw[TT];
    #pragma unroll
    for (int q = 0; q < TT; q++) xw[q] = sx4[q * CQ];

    ulonglong2 wk = sw4[0];
    #pragma unroll
    for (int k = 0; k < KK; k++) {
        ulonglong2 wnext = sw4[((k + 1) & (KK - 1)) * CQ];
        ulonglong2 xnew  = sx4[(k + TT) * CQ];     // row jbase+k+8 <= 127: in bounds

        #pragma unroll
        for (int j = 0; j < TT; j++) {
            ulonglong2 xv = xw[(k + j) & (TT - 1)];
            accA[j] = ffma2(xv.x, wk.x, accA[j]);
            accB[j] = ffma2(xv.y, wk.y, accB[j]);
        }

        xw[k & (TT - 1)] = xnew;
        wk = wnext;
    }

    // ---- tanh + store (16B/lane, coalesced within half) ----
    float4* outp = (float4*)out;          // full row = CC/4 = 32 float4
    const size_t ob = ((size_t)b * LL + t0 + jbase) * 32 + half * CQ + c4;
    #pragma unroll
    for (int j = 0; j < TT; j++) {
        float2 a = *(float2*)&accA[j];
        float2 c = *(float2*)&accB[j];
        outp[ob + (size_t)j * 32] =
            make_float4(tanh5(a.x), tanh5(a.y), tanh5(c.x), tanh5(c.y));
    }
}

extern "C" void kernel_launch(void* const* d_in, const int* in_sizes, int n_in,
                              void* d_out, int out_size) {
    const float* x    = (const float*)d_in[0];
    const float* w    = (const float*)d_in[1];
    const float* bias = (const float*)d_in[2];
    float*       out  = (float*)d_out;

    cudaFuncSetAttribute(dwconv1d_tanh_c4_kernel,
                         cudaFuncAttributeMaxDynamicSharedMemorySize, SMEM_BYTES);

    // grid: b (32) x tile (512) x half (2); halves adjacent for L2 halo reuse
    dwconv1d_tanh_c4_kernel<<<BB * (LL / TL) * 2, NTHREADS, SMEM_BYTES>>>(x, w, bias, out);
}

// round 15
// speedup vs baseline: 1.0803x; 1.0803x over previous
#include <cuda_runtime.h>
#include <cstddef>

#define BB       32
#define LL       32768
#define CC       128
#define KK       64
#define PADL     31          // SAME, K even: out[t] = sum_k x[t+k-31] * w[k]

#define CH       64          // channels per CTA (half of CC)
#define CP       32          // channel pairs per CTA
#define TL       128         // output rows per CTA
#define ROWS     192         // staged x rows: [t0-31, t0+160]
#define NTHREADS 256
#define TSUB     8
#define TT       (TL / TSUB) // 16 outputs per thread

#define SMEM_X_F (ROWS * CH)              // 12288 floats = 48 KB
#define SMEM_W_F (KK * CH)                // 4096 floats  = 16 KB
#define SMEM_BYTES ((SMEM_X_F + SMEM_W_F) * 4)   // 65536 B -> 3 CTAs/SM

typedef unsigned long long ull;

// Blackwell packed dual-FMA (FFMA2 in SASS): 2x fp32 FMA per issue.
__device__ __forceinline__ ull ffma2(ull a, ull b, ull c) {
    ull d;
    asm("fma.rn.f32x2 %0, %1, %2, %3;" : "=l"(d) : "l"(a), "l"(b), "l"(c));
    return d;
}
__device__ __forceinline__ ull pack2(float lo, float hi) {
    ull r;
    asm("mov.b64 %0, {%1, %2};" : "=l"(r) : "f"(lo), "f"(hi));
    return r;
}

// tanh(x) = 1 - 2/(e^{2x}+1), 5 instructions, branch-free. abs err ~2e-7.
__device__ __forceinline__ float tanh5(float x) {
    float s = x * 2.885390082f;        // 2*log2(e)
    float t, r;
    asm("ex2.approx.f32 %0, %1;" : "=f"(t) : "f"(s));
    float d = t + 1.0f;
    asm("rcp.approx.f32 %0, %1;" : "=f"(r) : "f"(d));
    return __fmaf_rn(-2.0f, r, 1.0f);
}

__global__ __launch_bounds__(NTHREADS, 3)
void dwconv1d_tanh_t16_kernel(const float* __restrict__ x,
                              const float* __restrict__ w,     // [K][CC]
                              const float* __restrict__ bias,  // [CC]
                              float* __restrict__ out) {
    extern __shared__ float sm[];
    float* sx = sm;                  // [ROWS][CH]
    float* sw = sm + SMEM_X_F;       // [KK][CH]

    const int tid  = threadIdx.x;
    const int blk  = blockIdx.x;
    const int half = blk & 1;                 // channel half
    const int tile = (blk >> 1) & 255;        // LL/TL = 256 tiles
    const int b    = blk >> 9;
    const int t0   = tile * TL;

    // ---- stage weights half: 64 rows x 16 float4 ----
    {
        const float4* wsrc = (const float4*)w;    // row stride CC/4 = 32
        float4*       wdst = (float4*)sw;
        #pragma unroll
        for (int n = 0; n < (SMEM_W_F / 4) / NTHREADS; n++) {   // 4 iters
            int idx = tid + n * NTHREADS;         // 0..1023
            int k   = idx >> 4;
            int col = idx & 15;
            wdst[idx] = wsrc[k * 32 + half * 16 + col];
        }
    }

    // ---- stage x half-rows [t0-31, t0+161), zero-padded ----
    {
        const int base = t0 - PADL;
        const float4* xsrc = (const float4*)(x + (size_t)b * LL * CC); // row stride 32 f4
        float4*       xdst = (float4*)sx;                              // row stride 16 f4
        #pragma unroll
        for (int n = 0; n < (SMEM_X_F / 4) / NTHREADS; n++) {   // 12 iters
            int idx = tid + n * NTHREADS;         // 0..3071
            int r   = idx >> 4;
            int col = idx & 15;
            int g   = base + r;
            float4 v = make_float4(0.f, 0.f, 0.f, 0.f);
            if ((unsigned)g < (unsigned)LL)
                v = xsrc[(size_t)g * 32 + half * 16 + col];
            xdst[idx] = v;
        }
    }
    __syncthreads();

    const int c2    = tid & (CP - 1);   // channel pair within half
    const int ts    = tid >> 5;         // 0..7 (warp-uniform)
    const int jbase = ts * TT;

    // Immediate-offset LDS bases (row stride CP ull = 256 B).
    const ull* sx2 = ((const ull*)sx) + (size_t)jbase * CP + c2;
    const ull* sw2 = ((const ull*)sw) + c2;

    // bias folded into accumulator init
    const float2 bv = ((const float2*)bias)[half * CP + c2];
    const ull bpair = pack2(bv.x, bv.y);
    ull acc[TT];
    #pragma unroll
    for (int j = 0; j < TT; j++) acc[j] = bpair;

    // Rolling 16-row register window: xw[(k+j)&15] = shared row (jbase+k+j).
    ull xw[TT];
    #pragma unroll
    for (int q = 0; q < TT; q++) xw[q] = sx2[q * CP];

    #pragma unroll
    for (int k = 0; k < KK; k++) {
        ull wk   = sw2[k * CP];
        ull xnew = sx2[(k + TT) * CP];   // row jbase+k+16 <= 191: in bounds

        #pragma unroll
        for (int j = 0; j < TT; j++)
            acc[j] = ffma2(xw[(k + j) & (TT - 1)], wk, acc[j]);

        xw[k & (TT - 1)] = xnew;
    }

    // ---- tanh + store (8B/lane, coalesced within half) ----
    float2* outp = (float2*)out;          // row stride CC/2 = 64 float2
    const size_t ob = ((size_t)b * LL + t0 + jbase) * 64 + half * CP + c2;
    #pragma unroll
    for (int j = 0; j < TT; j++) {
        float2 a = *(float2*)&acc[j];
        outp[ob + (size_t)j * 64] = make_float2(tanh5(a.x), tanh5(a.y));
    }
}

extern "C" void kernel_launch(void* const* d_in, const int* in_sizes, int n_in,
                              void* d_out, int out_size) {
    const float* x    = (const float*)d_in[0];
    const float* w    = (const float*)d_in[1];
    const float* bias = (const float*)d_in[2];
    float*       out  = (float*)d_out;

    cudaFuncSetAttribute(dwconv1d_tanh_t16_kernel,
                         cudaFuncAttributeMaxDynamicSharedMemorySize, SMEM_BYTES);

    // grid: b (32) x tile (256) x half (2); halves adjacent for L2 halo reuse
    dwconv1d_tanh_t16_kernel<<<BB * (LL / TL) * 2, NTHREADS, SMEM_BYTES>>>(x, w, bias, out);
}